// round 1
// baseline (speedup 1.0000x reference)
#include <cuda_runtime.h>
#include <cuda_bf16.h>
#include <math.h>

// Problem constants
#define SEQ_LEN   512
#define PRED_LEN  96
#define PATCH_LEN 16
#define STRIDE    8
#define NQ        4
#define NLAYERS   3
#define NPATCH    63           // (512-16)/8+1
#define BATCH     32
#define CHANS     128
#define NCH       (BATCH*CHANS)        // 4096
#define FAN_IN    (NPATCH*NQ)          // 252
#define NPAIR     136                  // 16*17/2

// Scratch (device globals; no allocation allowed)
__device__ float4 d_Mpk[NPAIR];                 // packed symmetric quad-form matrices (4 wires in .x..w)
__device__ float  d_encT[FAN_IN * NCH];         // enc transposed: [f][n]

// ---------------------------------------------------------------------------
// Kernel 1: build circuit unitary U (16x16 complex) and fold into quadratic
// forms M_i = Re(U^dag Z_i U). Pack as 136 float4 (upper triangle, off-diag x2).
// ---------------------------------------------------------------------------
__global__ void build_M_kernel(const float* __restrict__ weights) {
    __shared__ float2 sU[16][16];   // sU[k][c] : amplitude k of circuit applied to basis c
    int tid = threadIdx.x;

    if (tid < 16) {
        const int c = tid;
        float2 col[16];
        #pragma unroll
        for (int k = 0; k < 16; k++) col[k] = make_float2(k == c ? 1.f : 0.f, 0.f);

        for (int l = 0; l < NLAYERS; l++) {
            for (int w = 0; w < NQ; w++) {
                float phi   = weights[(l*NQ + w)*3 + 0];
                float theta = weights[(l*NQ + w)*3 + 1];
                float omega = weights[(l*NQ + w)*3 + 2];
                float ct = cosf(0.5f*theta), st = sinf(0.5f*theta);
                float ap = 0.5f*(phi + omega);   // m00 = e^{-i*ap} ct ; m11 = e^{+i*ap} ct
                float am = 0.5f*(phi - omega);   // m01 = -e^{+i*am} st ; m10 = e^{-i*am} st
                float cap = cosf(ap), sap = sinf(ap);
                float cam = cosf(am), sam = sinf(am);
                float2 m00 = make_float2( cap*ct, -sap*ct);
                float2 m11 = make_float2( cap*ct,  sap*ct);
                float2 m01 = make_float2(-cam*st, -sam*st);
                float2 m10 = make_float2( cam*st, -sam*st);
                int bit = 1 << (3 - w);
                #pragma unroll
                for (int k0 = 0; k0 < 16; k0++) {
                    if (k0 & bit) continue;
                    int k1 = k0 | bit;
                    float2 a = col[k0], b = col[k1];
                    col[k0] = make_float2(m00.x*a.x - m00.y*a.y + m01.x*b.x - m01.y*b.y,
                                          m00.x*a.y + m00.y*a.x + m01.x*b.y + m01.y*b.x);
                    col[k1] = make_float2(m10.x*a.x - m10.y*a.y + m11.x*b.x - m11.y*b.y,
                                          m10.x*a.y + m10.y*a.x + m11.x*b.y + m11.y*b.x);
                }
            }
            int r = (l % (NQ - 1)) + 1;
            for (int w = 0; w < NQ; w++) {
                int cb = 1 << (3 - w);
                int tb = 1 << (3 - ((w + r) & 3));
                #pragma unroll
                for (int k = 0; k < 16; k++) {
                    if ((k & cb) && !(k & tb)) {
                        float2 t = col[k]; col[k] = col[k | tb]; col[k | tb] = t;
                    }
                }
            }
        }
        #pragma unroll
        for (int k = 0; k < 16; k++) sU[k][c] = col[k];
    }
    __syncthreads();

    if (tid < NPAIR) {
        // map linear pair index -> (a,b) with a<=b
        int a = 0, rem = tid;
        while (rem >= 16 - a) { rem -= 16 - a; a++; }
        int b = a + rem;

        float s[4] = {0.f, 0.f, 0.f, 0.f};
        #pragma unroll
        for (int k = 0; k < 16; k++) {
            float2 ua = sU[k][a], ub = sU[k][b];
            float re = ua.x*ub.x + ua.y*ub.y;      // Re(conj(U[k][a]) * U[k][b])
            #pragma unroll
            for (int i = 0; i < 4; i++)
                s[i] += ((k >> (3 - i)) & 1) ? -re : re;
        }
        float scale = (a == b) ? 1.f : 2.f;
        d_Mpk[tid] = make_float4(s[0]*scale, s[1]*scale, s[2]*scale, s[3]*scale);
    }
}

// ---------------------------------------------------------------------------
// Kernel 2: per (channel, patch) quadratic forms -> encT[(j*4+i)*4096 + n]
// thread tid: n = tid & 4095 (coalesced across warp), j = tid >> 12
// ---------------------------------------------------------------------------
__global__ __launch_bounds__(256) void enc_kernel(const float* __restrict__ x) {
    __shared__ float4 sMp[NPAIR];
    if (threadIdx.x < NPAIR) sMp[threadIdx.x] = d_Mpk[threadIdx.x];
    __syncthreads();

    int tid = blockIdx.x * 256 + threadIdx.x;   // grid sized exactly 63*4096
    int n = tid & (NCH - 1);
    int j = tid >> 12;
    int b = n >> 7;
    int m = n & (CHANS - 1);

    const float* xp = x + (size_t)b * (SEQ_LEN*CHANS) + (size_t)(j*STRIDE) * CHANS + m;
    float v[16];
    float nrm2 = 0.f;
    #pragma unroll
    for (int k = 0; k < 16; k++) {
        float val = xp[k * CHANS] + 1e-6f;
        v[k] = val;
        nrm2 += val * val;
    }

    float z0 = 0.f, z1 = 0.f, z2 = 0.f, z3 = 0.f;
    int p = 0;
    #pragma unroll
    for (int a = 0; a < 16; a++) {
        #pragma unroll
        for (int bb = a; bb < 16; bb++) {
            float u = v[a] * v[bb];
            float4 mm = sMp[p++];
            z0 = fmaf(u, mm.x, z0);
            z1 = fmaf(u, mm.y, z1);
            z2 = fmaf(u, mm.z, z2);
            z3 = fmaf(u, mm.w, z3);
        }
    }
    float inv = 1.0f / nrm2;
    float* e = d_encT + (size_t)(j*4) * NCH + n;
    e[0*NCH] = z0 * inv;
    e[1*NCH] = z1 * inv;
    e[2*NCH] = z2 * inv;
    e[3*NCH] = z3 * inv;
}

// ---------------------------------------------------------------------------
// Kernel 3: out[b,o,m] = head_b[o] + skip_b[o]
//                        + sum_f head_w[o,f] * encT[f, b*128+m]
//                        + sum_l skip_w[o,l] * x[b,l,m]
// grid: (6 o-tiles of 16, 32 batches), block 128 threads (one per m)
// ---------------------------------------------------------------------------
#define OTILE 16
__global__ __launch_bounds__(128) void out_kernel(
    const float* __restrict__ x,
    const float* __restrict__ head_w, const float* __restrict__ head_b,
    const float* __restrict__ skip_w, const float* __restrict__ skip_b,
    float* __restrict__ out)
{
    __shared__ float sHW[OTILE * FAN_IN];    // 16*252
    __shared__ float sSW[OTILE * SEQ_LEN];   // 16*512

    int m  = threadIdx.x;
    int b  = blockIdx.y;
    int o0 = blockIdx.x * OTILE;

    for (int idx = threadIdx.x; idx < OTILE * FAN_IN; idx += 128)
        sHW[idx] = head_w[(size_t)o0 * FAN_IN + idx];
    for (int idx = threadIdx.x; idx < OTILE * SEQ_LEN; idx += 128)
        sSW[idx] = skip_w[(size_t)o0 * SEQ_LEN + idx];
    __syncthreads();

    int n = b * CHANS + m;
    float acc[OTILE];
    #pragma unroll
    for (int t = 0; t < OTILE; t++) acc[t] = head_b[o0 + t] + skip_b[o0 + t];

    const float* ep = d_encT + n;
    #pragma unroll 4
    for (int f = 0; f < FAN_IN; f++) {
        float e = ep[(size_t)f * NCH];
        #pragma unroll
        for (int t = 0; t < OTILE; t++)
            acc[t] = fmaf(sHW[t * FAN_IN + f], e, acc[t]);
    }

    const float* xp = x + (size_t)b * (SEQ_LEN*CHANS) + m;
    #pragma unroll 4
    for (int l = 0; l < SEQ_LEN; l++) {
        float xv = xp[(size_t)l * CHANS];
        #pragma unroll
        for (int t = 0; t < OTILE; t++)
            acc[t] = fmaf(sSW[t * SEQ_LEN + l], xv, acc[t]);
    }

    float* op = out + (size_t)b * (PRED_LEN*CHANS) + (size_t)o0 * CHANS + m;
    #pragma unroll
    for (int t = 0; t < OTILE; t++) op[t * CHANS] = acc[t];
}

// ---------------------------------------------------------------------------
extern "C" void kernel_launch(void* const* d_in, const int* in_sizes, int n_in,
                              void* d_out, int out_size) {
    const float* x       = (const float*)d_in[0];
    const float* weights = (const float*)d_in[1];
    const float* head_w  = (const float*)d_in[2];
    const float* head_b  = (const float*)d_in[3];
    const float* skip_w  = (const float*)d_in[4];
    const float* skip_b  = (const float*)d_in[5];
    float* out = (float*)d_out;

    build_M_kernel<<<1, 256>>>(weights);
    enc_kernel<<<(NPATCH * NCH) / 256, 256>>>(x);
    out_kernel<<<dim3(PRED_LEN / OTILE, BATCH), 128>>>(x, head_w, head_b, skip_w, skip_b, out);
}

// round 2
// speedup vs baseline: 1.0932x; 1.0932x over previous
#include <cuda_runtime.h>
#include <cuda_bf16.h>
#include <math.h>

// Problem constants
#define SEQ_LEN   512
#define PRED_LEN  96
#define PATCH_LEN 16
#define STRIDE    8
#define NQ        4
#define NLAYERS   3
#define NPATCH    63           // (512-16)/8+1
#define BATCH     32
#define CHANS     128
#define NCH       (BATCH*CHANS)        // 4096
#define FAN_IN    (NPATCH*NQ)          // 252
#define NPAIR     136                  // 16*17/2

typedef unsigned long long ull;

// ---- packed f32x2 helpers (sm_103a) ---------------------------------------
__device__ __forceinline__ ull fma2(ull a, ull b, ull c) {
    ull d; asm("fma.rn.f32x2 %0, %1, %2, %3;" : "=l"(d) : "l"(a), "l"(b), "l"(c)); return d;
}
__device__ __forceinline__ ull mul2(ull a, ull b) {
    ull d; asm("mul.rn.f32x2 %0, %1, %2;" : "=l"(d) : "l"(a), "l"(b)); return d;
}
__device__ __forceinline__ ull add2(ull a, ull b) {
    ull d; asm("add.rn.f32x2 %0, %1, %2;" : "=l"(d) : "l"(a), "l"(b)); return d;
}
__device__ __forceinline__ ull pack2(float lo, float hi) {
    ull d; asm("mov.b64 %0, {%1, %2};" : "=l"(d) : "f"(lo), "f"(hi)); return d;
}
__device__ __forceinline__ float lo2(ull a) { return __uint_as_float((unsigned)(a & 0xffffffffull)); }
__device__ __forceinline__ float hi2(ull a) { return __uint_as_float((unsigned)(a >> 32)); }

// Scratch (device globals; no allocation allowed)
__device__ float4 d_Mpk[NPAIR];                 // packed symmetric quad-form matrices (4 wires)
__device__ float  d_encT[FAN_IN * NCH];         // enc transposed: [f][n]

// ---------------------------------------------------------------------------
// Kernel 1: build circuit unitary U (16x16 complex) and fold into quadratic
// forms M_i = Re(U^dag Z_i U). Pack as 136 float4 (upper tri, off-diag x2).
// Phase A: 12 threads compute gate matrices in parallel (hides weight-load
// latency + MUFU outside the serial chain). Phase B: 16 column threads apply
// gates from shared. Phase C: 136 threads fold pairs.
// ---------------------------------------------------------------------------
__global__ void build_M_kernel(const float* __restrict__ weights) {
    __shared__ float2 sG[12][4];    // m00, m01, m10, m11 per gate
    __shared__ float2 sU[16][16];   // sU[k][c]
    int tid = threadIdx.x;

    if (tid < 12) {
        float phi   = weights[tid*3 + 0];
        float theta = weights[tid*3 + 1];
        float omega = weights[tid*3 + 2];
        float ct = cosf(0.5f*theta), st = sinf(0.5f*theta);
        float ap = 0.5f*(phi + omega);
        float am = 0.5f*(phi - omega);
        float cap = cosf(ap), sap = sinf(ap);
        float cam = cosf(am), sam = sinf(am);
        sG[tid][0] = make_float2( cap*ct, -sap*ct);   // m00
        sG[tid][1] = make_float2(-cam*st, -sam*st);   // m01
        sG[tid][2] = make_float2( cam*st, -sam*st);   // m10
        sG[tid][3] = make_float2( cap*ct,  sap*ct);   // m11
    }
    __syncthreads();

    if (tid < 16) {
        const int c = tid;
        float2 col[16];
        #pragma unroll
        for (int k = 0; k < 16; k++) col[k] = make_float2(k == c ? 1.f : 0.f, 0.f);

        #pragma unroll
        for (int l = 0; l < NLAYERS; l++) {
            #pragma unroll
            for (int w = 0; w < NQ; w++) {
                float2 m00 = sG[l*NQ + w][0], m01 = sG[l*NQ + w][1];
                float2 m10 = sG[l*NQ + w][2], m11 = sG[l*NQ + w][3];
                int bit = 1 << (3 - w);
                #pragma unroll
                for (int k0 = 0; k0 < 16; k0++) {
                    if (k0 & bit) continue;
                    int k1 = k0 | bit;
                    float2 a = col[k0], b = col[k1];
                    col[k0] = make_float2(m00.x*a.x - m00.y*a.y + m01.x*b.x - m01.y*b.y,
                                          m00.x*a.y + m00.y*a.x + m01.x*b.y + m01.y*b.x);
                    col[k1] = make_float2(m10.x*a.x - m10.y*a.y + m11.x*b.x - m11.y*b.y,
                                          m10.x*a.y + m10.y*a.x + m11.x*b.y + m11.y*b.x);
                }
            }
            int r = (l % (NQ - 1)) + 1;
            #pragma unroll
            for (int w = 0; w < NQ; w++) {
                int cb = 1 << (3 - w);
                int tb = 1 << (3 - ((w + r) & 3));
                #pragma unroll
                for (int k = 0; k < 16; k++) {
                    if ((k & cb) && !(k & tb)) {
                        float2 t = col[k]; col[k] = col[k | tb]; col[k | tb] = t;
                    }
                }
            }
        }
        #pragma unroll
        for (int k = 0; k < 16; k++) sU[k][c] = col[k];
    }
    __syncthreads();

    if (tid < NPAIR) {
        int a = 0, rem = tid;
        while (rem >= 16 - a) { rem -= 16 - a; a++; }
        int b = a + rem;

        float s[4] = {0.f, 0.f, 0.f, 0.f};
        #pragma unroll
        for (int k = 0; k < 16; k++) {
            float2 ua = sU[k][a], ub = sU[k][b];
            float re = ua.x*ub.x + ua.y*ub.y;
            #pragma unroll
            for (int i = 0; i < 4; i++)
                s[i] += ((k >> (3 - i)) & 1) ? -re : re;
        }
        float scale = (a == b) ? 1.f : 2.f;
        d_Mpk[tid] = make_float4(s[0]*scale, s[1]*scale, s[2]*scale, s[3]*scale);
    }
}

// ---------------------------------------------------------------------------
// Kernel 2: quadratic forms, 2 channels per thread via f32x2.
// tid -> (j, n-pair). x loads are LDG.64 coalesced; M duplicated in shared.
// ---------------------------------------------------------------------------
__global__ __launch_bounds__(256) void enc_kernel(const float* __restrict__ x) {
    __shared__ ulonglong2 sM[NPAIR * 2];   // per pair: (mx|mx, my|my), (mz|mz, mw|mw)
    if (threadIdx.x < NPAIR) {
        float4 mm = d_Mpk[threadIdx.x];
        ulonglong2 a, b;
        a.x = pack2(mm.x, mm.x); a.y = pack2(mm.y, mm.y);
        b.x = pack2(mm.z, mm.z); b.y = pack2(mm.w, mm.w);
        sM[threadIdx.x*2 + 0] = a;
        sM[threadIdx.x*2 + 1] = b;
    }
    __syncthreads();

    int tid = blockIdx.x * 256 + threadIdx.x;   // grid = 63*2048 threads
    int h = tid & 2047;
    int j = tid >> 11;
    int n0 = h << 1;
    int b  = n0 >> 7;
    int m  = n0 & 127;

    const ull* xp = (const ull*)(x + (size_t)b * (SEQ_LEN*CHANS)
                                   + (size_t)(j*STRIDE) * CHANS + m);
    const ull EPS2 = 0x358637bd358637bdULL;   // (1e-6f, 1e-6f)

    ull v[16];
    ull nrm2 = 0ULL;
    #pragma unroll
    for (int k = 0; k < 16; k++) {
        ull val = xp[k * (CHANS/2)];
        val = add2(val, EPS2);
        v[k] = val;
        nrm2 = fma2(val, val, nrm2);
    }

    ull z0 = 0ULL, z1 = 0ULL, z2 = 0ULL, z3 = 0ULL;
    int p = 0;
    #pragma unroll
    for (int a = 0; a < 16; a++) {
        #pragma unroll
        for (int bb = a; bb < 16; bb++) {
            ull u = mul2(v[a], v[bb]);
            ulonglong2 q0 = sM[2*p + 0];
            ulonglong2 q1 = sM[2*p + 1];
            z0 = fma2(u, q0.x, z0);
            z1 = fma2(u, q0.y, z1);
            z2 = fma2(u, q1.x, z2);
            z3 = fma2(u, q1.y, z3);
            p++;
        }
    }
    float inv0 = 1.0f / lo2(nrm2);
    float inv1 = 1.0f / hi2(nrm2);
    ull inv2 = pack2(inv0, inv1);

    ull* e = (ull*)(d_encT + (size_t)(j*4) * NCH + n0);
    e[0*(NCH/2)] = mul2(z0, inv2);
    e[1*(NCH/2)] = mul2(z1, inv2);
    e[2*(NCH/2)] = mul2(z2, inv2);
    e[3*(NCH/2)] = mul2(z3, inv2);
}

// ---------------------------------------------------------------------------
// Kernel 3: fused head+skip GEMM, f32x2 packed across output-row pairs.
// grid (6 o-tiles, 32 b, 2 m-halves), 64 threads (one per m).
// Weights staged in one reused 32KB shared buffer (head first, then skip).
// ---------------------------------------------------------------------------
#define OTILE 16
__global__ __launch_bounds__(64) void out_kernel(
    const float* __restrict__ x,
    const float* __restrict__ head_w, const float* __restrict__ head_b,
    const float* __restrict__ skip_w, const float* __restrict__ skip_b,
    float* __restrict__ out)
{
    __shared__ float sW[OTILE * SEQ_LEN];   // 16*512 floats = 32KB, reused

    int tid = threadIdx.x;                  // 0..63
    int b   = blockIdx.y;
    int o0  = blockIdx.x * OTILE;
    int m   = blockIdx.z * 64 + tid;
    int n   = b * CHANS + m;

    // --- stage head weights transposed: sW[f*16 + oi] = head_w[o0+oi][f]
    for (int idx = tid; idx < OTILE * FAN_IN; idx += 64) {
        int oi = idx / FAN_IN, f = idx - oi * FAN_IN;
        sW[f * OTILE + oi] = head_w[(size_t)(o0 + oi) * FAN_IN + f];
    }
    __syncthreads();

    ull acc[8];
    #pragma unroll
    for (int t = 0; t < 8; t++)
        acc[t] = pack2(head_b[o0 + 2*t]     + skip_b[o0 + 2*t],
                       head_b[o0 + 2*t + 1] + skip_b[o0 + 2*t + 1]);

    const float* ep = d_encT + n;
    const ulonglong2* w2 = (const ulonglong2*)sW;
    #pragma unroll 4
    for (int f = 0; f < FAN_IN; f++) {
        float e = ep[(size_t)f * NCH];
        ull e2 = pack2(e, e);
        ulonglong2 p0 = w2[f*4 + 0], p1 = w2[f*4 + 1];
        ulonglong2 p2 = w2[f*4 + 2], p3 = w2[f*4 + 3];
        acc[0] = fma2(e2, p0.x, acc[0]);  acc[1] = fma2(e2, p0.y, acc[1]);
        acc[2] = fma2(e2, p1.x, acc[2]);  acc[3] = fma2(e2, p1.y, acc[3]);
        acc[4] = fma2(e2, p2.x, acc[4]);  acc[5] = fma2(e2, p2.y, acc[5]);
        acc[6] = fma2(e2, p3.x, acc[6]);  acc[7] = fma2(e2, p3.y, acc[7]);
    }
    __syncthreads();

    // --- stage skip weights transposed: sW[l*16 + oi] = skip_w[o0+oi][l]
    for (int idx = tid; idx < OTILE * SEQ_LEN; idx += 64) {
        int oi = idx >> 9, l = idx & 511;
        sW[l * OTILE + oi] = skip_w[(size_t)(o0 + oi) * SEQ_LEN + l];
    }
    __syncthreads();

    const float* xp = x + (size_t)b * (SEQ_LEN*CHANS) + m;
    #pragma unroll 4
    for (int l = 0; l < SEQ_LEN; l++) {
        float xv = xp[(size_t)l * CHANS];
        ull x2 = pack2(xv, xv);
        ulonglong2 p0 = w2[l*4 + 0], p1 = w2[l*4 + 1];
        ulonglong2 p2 = w2[l*4 + 2], p3 = w2[l*4 + 3];
        acc[0] = fma2(x2, p0.x, acc[0]);  acc[1] = fma2(x2, p0.y, acc[1]);
        acc[2] = fma2(x2, p1.x, acc[2]);  acc[3] = fma2(x2, p1.y, acc[3]);
        acc[4] = fma2(x2, p2.x, acc[4]);  acc[5] = fma2(x2, p2.y, acc[5]);
        acc[6] = fma2(x2, p3.x, acc[6]);  acc[7] = fma2(x2, p3.y, acc[7]);
    }

    float* op = out + (size_t)b * (PRED_LEN*CHANS) + (size_t)o0 * CHANS + m;
    #pragma unroll
    for (int t = 0; t < 8; t++) {
        op[(2*t)     * CHANS] = lo2(acc[t]);
        op[(2*t + 1) * CHANS] = hi2(acc[t]);
    }
}

// ---------------------------------------------------------------------------
extern "C" void kernel_launch(void* const* d_in, const int* in_sizes, int n_in,
                              void* d_out, int out_size) {
    const float* x       = (const float*)d_in[0];
    const float* weights = (const float*)d_in[1];
    const float* head_w  = (const float*)d_in[2];
    const float* head_b  = (const float*)d_in[3];
    const float* skip_w  = (const float*)d_in[4];
    const float* skip_b  = (const float*)d_in[5];
    float* out = (float*)d_out;

    build_M_kernel<<<1, 192>>>(weights);
    enc_kernel<<<(NPATCH * NCH / 2) / 256, 256>>>(x);
    out_kernel<<<dim3(PRED_LEN / OTILE, BATCH, 2), 64>>>(x, head_w, head_b, skip_w, skip_b, out);
}

// round 3
// speedup vs baseline: 1.2336x; 1.1285x over previous
#include <cuda_runtime.h>
#include <cuda_bf16.h>
#include <math.h>

// Problem constants
#define SEQ_LEN   512
#define PRED_LEN  96
#define PATCH_LEN 16
#define STRIDE    8
#define NQ        4
#define NLAYERS   3
#define NPATCH    63           // (512-16)/8+1
#define BATCH     32
#define CHANS     128
#define NCH       (BATCH*CHANS)        // 4096
#define FAN_IN    (NPATCH*NQ)          // 252
#define NPAIR     136                  // 16*17/2

typedef unsigned long long ull;

// ---- packed f32x2 helpers (sm_103a) ---------------------------------------
__device__ __forceinline__ ull fma2(ull a, ull b, ull c) {
    ull d; asm("fma.rn.f32x2 %0, %1, %2, %3;" : "=l"(d) : "l"(a), "l"(b), "l"(c)); return d;
}
__device__ __forceinline__ ull mul2(ull a, ull b) {
    ull d; asm("mul.rn.f32x2 %0, %1, %2;" : "=l"(d) : "l"(a), "l"(b)); return d;
}
__device__ __forceinline__ ull add2(ull a, ull b) {
    ull d; asm("add.rn.f32x2 %0, %1, %2;" : "=l"(d) : "l"(a), "l"(b)); return d;
}
__device__ __forceinline__ ull pack2(float lo, float hi) {
    ull d; asm("mov.b64 %0, {%1, %2};" : "=l"(d) : "f"(lo), "f"(hi)); return d;
}
__device__ __forceinline__ float lo2(ull a) { return __uint_as_float((unsigned)(a & 0xffffffffull)); }
__device__ __forceinline__ float hi2(ull a) { return __uint_as_float((unsigned)(a >> 32)); }

// Scratch (device globals; no allocation allowed)
__device__ float  d_encT[FAN_IN * NCH];         // enc transposed: [f][n]

// ---------------------------------------------------------------------------
// Kernel 1: encoder. Each block first builds the circuit's quadratic-form
// matrices M_i = Re(U^dag Z_i U) in shared memory (redundantly per block --
// cheaper than a dedicated launch), then computes z_i = v^T M_i v / |v|^2
// for 2 channels per thread via f32x2.
// ---------------------------------------------------------------------------
__global__ __launch_bounds__(256) void enc_kernel(const float* __restrict__ x,
                                                  const float* __restrict__ weights) {
    __shared__ float2 sG[12][4];            // gate matrices m00,m01,m10,m11
    __shared__ float2 sU[16][16];           // sU[k][c]
    __shared__ ulonglong2 sM[NPAIR * 2];    // duplicated-packed quad forms

    int tid = threadIdx.x;

    // ---- phase A: 12 threads compute gate matrices (parallel trig) ----
    if (tid < 12) {
        float phi   = weights[tid*3 + 0];
        float theta = weights[tid*3 + 1];
        float omega = weights[tid*3 + 2];
        float ct = cosf(0.5f*theta), st = sinf(0.5f*theta);
        float ap = 0.5f*(phi + omega);
        float am = 0.5f*(phi - omega);
        float cap = cosf(ap), sap = sinf(ap);
        float cam = cosf(am), sam = sinf(am);
        sG[tid][0] = make_float2( cap*ct, -sap*ct);   // m00
        sG[tid][1] = make_float2(-cam*st, -sam*st);   // m01
        sG[tid][2] = make_float2( cam*st, -sam*st);   // m10
        sG[tid][3] = make_float2( cap*ct,  sap*ct);   // m11
    }
    __syncthreads();

    // ---- phase B: 16 threads build U column-by-column ----
    if (tid < 16) {
        const int c = tid;
        float2 col[16];
        #pragma unroll
        for (int k = 0; k < 16; k++) col[k] = make_float2(k == c ? 1.f : 0.f, 0.f);

        #pragma unroll
        for (int l = 0; l < NLAYERS; l++) {
            #pragma unroll
            for (int w = 0; w < NQ; w++) {
                float2 m00 = sG[l*NQ + w][0], m01 = sG[l*NQ + w][1];
                float2 m10 = sG[l*NQ + w][2], m11 = sG[l*NQ + w][3];
                int bit = 1 << (3 - w);
                #pragma unroll
                for (int k0 = 0; k0 < 16; k0++) {
                    if (k0 & bit) continue;
                    int k1 = k0 | bit;
                    float2 a = col[k0], b = col[k1];
                    col[k0] = make_float2(m00.x*a.x - m00.y*a.y + m01.x*b.x - m01.y*b.y,
                                          m00.x*a.y + m00.y*a.x + m01.x*b.y + m01.y*b.x);
                    col[k1] = make_float2(m10.x*a.x - m10.y*a.y + m11.x*b.x - m11.y*b.y,
                                          m10.x*a.y + m10.y*a.x + m11.x*b.y + m11.y*b.x);
                }
            }
            int r = (l % (NQ - 1)) + 1;
            #pragma unroll
            for (int w = 0; w < NQ; w++) {
                int cb = 1 << (3 - w);
                int tb = 1 << (3 - ((w + r) & 3));
                #pragma unroll
                for (int k = 0; k < 16; k++) {
                    if ((k & cb) && !(k & tb)) {
                        float2 t = col[k]; col[k] = col[k | tb]; col[k | tb] = t;
                    }
                }
            }
        }
        #pragma unroll
        for (int k = 0; k < 16; k++) sU[k][c] = col[k];
    }
    __syncthreads();

    // ---- phase C: 136 threads fold U into packed quadratic forms ----
    if (tid < NPAIR) {
        int a = 0, rem = tid;
        while (rem >= 16 - a) { rem -= 16 - a; a++; }
        int b = a + rem;

        float s[4] = {0.f, 0.f, 0.f, 0.f};
        #pragma unroll
        for (int k = 0; k < 16; k++) {
            float2 ua = sU[k][a], ub = sU[k][b];
            float re = ua.x*ub.x + ua.y*ub.y;
            #pragma unroll
            for (int i = 0; i < 4; i++)
                s[i] += ((k >> (3 - i)) & 1) ? -re : re;
        }
        float scale = (a == b) ? 1.f : 2.f;
        ulonglong2 q0, q1;
        q0.x = pack2(s[0]*scale, s[0]*scale); q0.y = pack2(s[1]*scale, s[1]*scale);
        q1.x = pack2(s[2]*scale, s[2]*scale); q1.y = pack2(s[3]*scale, s[3]*scale);
        sM[tid*2 + 0] = q0;
        sM[tid*2 + 1] = q1;
    }
    __syncthreads();

    // ---- main: quadratic forms, 2 channels per thread ----
    int gtid = blockIdx.x * 256 + tid;      // grid = 63*2048 threads
    int h = gtid & 2047;
    int j = gtid >> 11;
    int n0 = h << 1;
    int b  = n0 >> 7;
    int m  = n0 & 127;

    const ull* xp = (const ull*)(x + (size_t)b * (SEQ_LEN*CHANS)
                                   + (size_t)(j*STRIDE) * CHANS + m);
    const ull EPS2 = 0x358637bd358637bdULL;   // (1e-6f, 1e-6f)

    ull v[16];
    #pragma unroll
    for (int k = 0; k < 16; k++)
        v[k] = add2(xp[k * (CHANS/2)], EPS2);

    ull z0 = 0ULL, z1 = 0ULL, z2 = 0ULL, z3 = 0ULL, nrm2 = 0ULL;
    int p = 0;
    #pragma unroll
    for (int a = 0; a < 16; a++) {
        #pragma unroll
        for (int bb = a; bb < 16; bb++) {
            ull u = mul2(v[a], v[bb]);
            if (bb == a) nrm2 = add2(nrm2, u);   // diag products = |v|^2 terms
            ulonglong2 q0 = sM[2*p + 0];
            ulonglong2 q1 = sM[2*p + 1];
            z0 = fma2(u, q0.x, z0);
            z1 = fma2(u, q0.y, z1);
            z2 = fma2(u, q1.x, z2);
            z3 = fma2(u, q1.y, z3);
            p++;
        }
    }
    float inv0 = 1.0f / lo2(nrm2);
    float inv1 = 1.0f / hi2(nrm2);
    ull inv2 = pack2(inv0, inv1);

    ull* e = (ull*)(d_encT + (size_t)(j*4) * NCH + n0);
    e[0*(NCH/2)] = mul2(z0, inv2);
    e[1*(NCH/2)] = mul2(z1, inv2);
    e[2*(NCH/2)] = mul2(z2, inv2);
    e[3*(NCH/2)] = mul2(z3, inv2);
}

// ---------------------------------------------------------------------------
// Kernel 2: fused head+skip GEMM. OTILE=8 output rows per thread (4 f32x2
// accs), 128 threads (one per channel m), grid (12 o-tiles, 32 batches).
// Deep unroll => ~16 outstanding L2 loads per warp to hide ~250cyc latency.
// ---------------------------------------------------------------------------
#define OTILE 8
__global__ __launch_bounds__(128) void out_kernel(
    const float* __restrict__ x,
    const float* __restrict__ head_w, const float* __restrict__ head_b,
    const float* __restrict__ skip_w, const float* __restrict__ skip_b,
    float* __restrict__ out)
{
    __shared__ float sW[OTILE * SEQ_LEN];   // 8*512 floats = 16KB, reused

    int tid = threadIdx.x;                  // 0..127 = m
    int b   = blockIdx.y;
    int o0  = blockIdx.x * OTILE;
    int m   = tid;
    int n   = b * CHANS + m;

    // stage head weights transposed: sW[f*8 + oi] = head_w[o0+oi][f]
    for (int idx = tid; idx < OTILE * FAN_IN; idx += 128) {
        int oi = idx / FAN_IN, f = idx - oi * FAN_IN;
        sW[f * OTILE + oi] = head_w[(size_t)(o0 + oi) * FAN_IN + f];
    }
    __syncthreads();

    ull acc[4];
    #pragma unroll
    for (int t = 0; t < 4; t++)
        acc[t] = pack2(head_b[o0 + 2*t]     + skip_b[o0 + 2*t],
                       head_b[o0 + 2*t + 1] + skip_b[o0 + 2*t + 1]);

    const float* ep = d_encT + n;
    const ulonglong2* w2 = (const ulonglong2*)sW;
    #pragma unroll 16
    for (int f = 0; f < FAN_IN; f++) {
        float e = __ldg(ep + (size_t)f * NCH);
        ull e2 = pack2(e, e);
        ulonglong2 q0 = w2[f*2 + 0], q1 = w2[f*2 + 1];
        acc[0] = fma2(e2, q0.x, acc[0]);  acc[1] = fma2(e2, q0.y, acc[1]);
        acc[2] = fma2(e2, q1.x, acc[2]);  acc[3] = fma2(e2, q1.y, acc[3]);
    }
    __syncthreads();

    // stage skip weights transposed: sW[l*8 + oi] = skip_w[o0+oi][l]
    for (int idx = tid; idx < OTILE * SEQ_LEN; idx += 128) {
        int oi = idx >> 9, l = idx & 511;
        sW[l * OTILE + oi] = skip_w[(size_t)(o0 + oi) * SEQ_LEN + l];
    }
    __syncthreads();

    const float* xp = x + (size_t)b * (SEQ_LEN*CHANS) + m;
    #pragma unroll 16
    for (int l = 0; l < SEQ_LEN; l++) {
        float xv = __ldg(xp + (size_t)l * CHANS);
        ull x2 = pack2(xv, xv);
        ulonglong2 q0 = w2[l*2 + 0], q1 = w2[l*2 + 1];
        acc[0] = fma2(x2, q0.x, acc[0]);  acc[1] = fma2(x2, q0.y, acc[1]);
        acc[2] = fma2(x2, q1.x, acc[2]);  acc[3] = fma2(x2, q1.y, acc[3]);
    }

    float* op = out + (size_t)b * (PRED_LEN*CHANS) + (size_t)o0 * CHANS + m;
    #pragma unroll
    for (int t = 0; t < 4; t++) {
        op[(2*t)     * CHANS] = lo2(acc[t]);
        op[(2*t + 1) * CHANS] = hi2(acc[t]);
    }
}

// ---------------------------------------------------------------------------
extern "C" void kernel_launch(void* const* d_in, const int* in_sizes, int n_in,
                              void* d_out, int out_size) {
    const float* x       = (const float*)d_in[0];
    const float* weights = (const float*)d_in[1];
    const float* head_w  = (const float*)d_in[2];
    const float* head_b  = (const float*)d_in[3];
    const float* skip_w  = (const float*)d_in[4];
    const float* skip_b  = (const float*)d_in[5];
    float* out = (float*)d_out;

    enc_kernel<<<(NPATCH * NCH / 2) / 256, 256>>>(x, weights);
    out_kernel<<<dim3(PRED_LEN / OTILE, BATCH), 128>>>(x, head_w, head_b, skip_w, skip_b, out);
}

// round 4
// speedup vs baseline: 1.3602x; 1.1026x over previous
#include <cuda_runtime.h>
#include <cuda_bf16.h>
#include <math.h>

// Problem constants
#define SEQ_LEN   512
#define PRED_LEN  96
#define PATCH_LEN 16
#define STRIDE    8
#define NQ        4
#define NLAYERS   3
#define NPATCH    63           // (512-16)/8+1
#define BATCH     32
#define CHANS     128
#define NCH       (BATCH*CHANS)        // 4096
#define FAN_IN    (NPATCH*NQ)          // 252
#define NPAIR     136                  // 16*17/2

typedef unsigned long long ull;

// ---- packed f32x2 helpers (sm_103a) ---------------------------------------
__device__ __forceinline__ ull fma2(ull a, ull b, ull c) {
    ull d; asm("fma.rn.f32x2 %0, %1, %2, %3;" : "=l"(d) : "l"(a), "l"(b), "l"(c)); return d;
}
__device__ __forceinline__ ull mul2(ull a, ull b) {
    ull d; asm("mul.rn.f32x2 %0, %1, %2;" : "=l"(d) : "l"(a), "l"(b)); return d;
}
__device__ __forceinline__ ull add2(ull a, ull b) {
    ull d; asm("add.rn.f32x2 %0, %1, %2;" : "=l"(d) : "l"(a), "l"(b)); return d;
}
__device__ __forceinline__ ull pack2(float lo, float hi) {
    ull d; asm("mov.b64 %0, {%1, %2};" : "=l"(d) : "f"(lo), "f"(hi)); return d;
}
__device__ __forceinline__ float lo2(ull a) { return __uint_as_float((unsigned)(a & 0xffffffffull)); }
__device__ __forceinline__ float hi2(ull a) { return __uint_as_float((unsigned)(a >> 32)); }

// Scratch (device globals; no allocation allowed)
__device__ float  d_encT[FAN_IN * NCH];         // enc transposed: [f][n]

// ---------------------------------------------------------------------------
// Kernel 1: encoder. Each block builds the circuit's quadratic-form matrices
// M_i = Re(U^dag Z_i U) in shared memory (redundant per block), then computes
// z_i = v^T M_i v / |v|^2 for 2 channels per thread via f32x2.
// ---------------------------------------------------------------------------
__global__ __launch_bounds__(256) void enc_kernel(const float* __restrict__ x,
                                                  const float* __restrict__ weights) {
    __shared__ float2 sG[12][4];            // gate matrices m00,m01,m10,m11
    __shared__ float2 sU[16][16];           // sU[k][c]
    __shared__ ulonglong2 sM[NPAIR * 2];    // duplicated-packed quad forms

    int tid = threadIdx.x;

    // ---- phase A: 12 threads compute gate matrices (parallel trig) ----
    if (tid < 12) {
        float phi   = weights[tid*3 + 0];
        float theta = weights[tid*3 + 1];
        float omega = weights[tid*3 + 2];
        float ct = cosf(0.5f*theta), st = sinf(0.5f*theta);
        float ap = 0.5f*(phi + omega);
        float am = 0.5f*(phi - omega);
        float cap = cosf(ap), sap = sinf(ap);
        float cam = cosf(am), sam = sinf(am);
        sG[tid][0] = make_float2( cap*ct, -sap*ct);   // m00
        sG[tid][1] = make_float2(-cam*st, -sam*st);   // m01
        sG[tid][2] = make_float2( cam*st, -sam*st);   // m10
        sG[tid][3] = make_float2( cap*ct,  sap*ct);   // m11
    }
    __syncthreads();

    // ---- phase B: 16 threads build U column-by-column ----
    if (tid < 16) {
        const int c = tid;
        float2 col[16];
        #pragma unroll
        for (int k = 0; k < 16; k++) col[k] = make_float2(k == c ? 1.f : 0.f, 0.f);

        #pragma unroll
        for (int l = 0; l < NLAYERS; l++) {
            #pragma unroll
            for (int w = 0; w < NQ; w++) {
                float2 m00 = sG[l*NQ + w][0], m01 = sG[l*NQ + w][1];
                float2 m10 = sG[l*NQ + w][2], m11 = sG[l*NQ + w][3];
                int bit = 1 << (3 - w);
                #pragma unroll
                for (int k0 = 0; k0 < 16; k0++) {
                    if (k0 & bit) continue;
                    int k1 = k0 | bit;
                    float2 a = col[k0], b = col[k1];
                    col[k0] = make_float2(m00.x*a.x - m00.y*a.y + m01.x*b.x - m01.y*b.y,
                                          m00.x*a.y + m00.y*a.x + m01.x*b.y + m01.y*b.x);
                    col[k1] = make_float2(m10.x*a.x - m10.y*a.y + m11.x*b.x - m11.y*b.y,
                                          m10.x*a.y + m10.y*a.x + m11.x*b.y + m11.y*b.x);
                }
            }
            int r = (l % (NQ - 1)) + 1;
            #pragma unroll
            for (int w = 0; w < NQ; w++) {
                int cb = 1 << (3 - w);
                int tb = 1 << (3 - ((w + r) & 3));
                #pragma unroll
                for (int k = 0; k < 16; k++) {
                    if ((k & cb) && !(k & tb)) {
                        float2 t = col[k]; col[k] = col[k | tb]; col[k | tb] = t;
                    }
                }
            }
        }
        #pragma unroll
        for (int k = 0; k < 16; k++) sU[k][c] = col[k];
    }
    __syncthreads();

    // ---- phase C: 136 threads fold U into packed quadratic forms ----
    if (tid < NPAIR) {
        int a = 0, rem = tid;
        while (rem >= 16 - a) { rem -= 16 - a; a++; }
        int b = a + rem;

        float s[4] = {0.f, 0.f, 0.f, 0.f};
        #pragma unroll
        for (int k = 0; k < 16; k++) {
            float2 ua = sU[k][a], ub = sU[k][b];
            float re = ua.x*ub.x + ua.y*ub.y;
            #pragma unroll
            for (int i = 0; i < 4; i++)
                s[i] += ((k >> (3 - i)) & 1) ? -re : re;
        }
        float scale = (a == b) ? 1.f : 2.f;
        ulonglong2 q0, q1;
        q0.x = pack2(s[0]*scale, s[0]*scale); q0.y = pack2(s[1]*scale, s[1]*scale);
        q1.x = pack2(s[2]*scale, s[2]*scale); q1.y = pack2(s[3]*scale, s[3]*scale);
        sM[tid*2 + 0] = q0;
        sM[tid*2 + 1] = q1;
    }
    __syncthreads();

    // ---- main: quadratic forms, 2 channels per thread ----
    int gtid = blockIdx.x * 256 + tid;      // grid = 63*2048 threads
    int h = gtid & 2047;
    int j = gtid >> 11;
    int n0 = h << 1;
    int b  = n0 >> 7;
    int m  = n0 & 127;

    const ull* xp = (const ull*)(x + (size_t)b * (SEQ_LEN*CHANS)
                                   + (size_t)(j*STRIDE) * CHANS + m);
    const ull EPS2 = 0x358637bd358637bdULL;   // (1e-6f, 1e-6f)

    ull v[16];
    #pragma unroll
    for (int k = 0; k < 16; k++)
        v[k] = add2(xp[k * (CHANS/2)], EPS2);

    ull z0 = 0ULL, z1 = 0ULL, z2 = 0ULL, z3 = 0ULL, nrm2 = 0ULL;
    int p = 0;
    #pragma unroll
    for (int a = 0; a < 16; a++) {
        #pragma unroll
        for (int bb = a; bb < 16; bb++) {
            ull u = mul2(v[a], v[bb]);
            if (bb == a) nrm2 = add2(nrm2, u);   // diag products = |v|^2 terms
            ulonglong2 q0 = sM[2*p + 0];
            ulonglong2 q1 = sM[2*p + 1];
            z0 = fma2(u, q0.x, z0);
            z1 = fma2(u, q0.y, z1);
            z2 = fma2(u, q1.x, z2);
            z3 = fma2(u, q1.y, z3);
            p++;
        }
    }
    float inv0 = 1.0f / lo2(nrm2);
    float inv1 = 1.0f / hi2(nrm2);
    ull inv2 = pack2(inv0, inv1);

    ull* e = (ull*)(d_encT + (size_t)(j*4) * NCH + n0);
    e[0*(NCH/2)] = mul2(z0, inv2);
    e[1*(NCH/2)] = mul2(z1, inv2);
    e[2*(NCH/2)] = mul2(z2, inv2);
    e[3*(NCH/2)] = mul2(z3, inv2);
}

// ---------------------------------------------------------------------------
// Kernel 2: fused head+skip GEMM.
// OTILE=4 output rows per thread (2 f32x2 accs), 128 threads (one per m),
// grid (24 o-tiles, 32 batches) = 768 blocks / 3072 warps.
// Loads are MANUALLY batched into register arrays (MLP 12/16) so L2 latency
// (~250cyc) is covered: chunk sizes 12 (252=21*12) and 16 (512=32*16).
// ---------------------------------------------------------------------------
#define OTILE 4
__global__ __launch_bounds__(128) void out_kernel(
    const float* __restrict__ x,
    const float* __restrict__ head_w, const float* __restrict__ head_b,
    const float* __restrict__ skip_w, const float* __restrict__ skip_b,
    float* __restrict__ out)
{
    __shared__ float sW[OTILE * SEQ_LEN];   // 4*512 floats = 8KB, reused

    int tid = threadIdx.x;                  // 0..127 = m
    int b   = blockIdx.y;
    int o0  = blockIdx.x * OTILE;
    int m   = tid;
    int n   = b * CHANS + m;

    // stage head weights transposed: sW[f*4 + oi] = head_w[o0+oi][f]
    for (int idx = tid; idx < OTILE * FAN_IN; idx += 128) {
        int oi = idx / FAN_IN, f = idx - oi * FAN_IN;
        sW[f * OTILE + oi] = head_w[(size_t)(o0 + oi) * FAN_IN + f];
    }
    __syncthreads();

    ull acc0 = pack2(head_b[o0 + 0] + skip_b[o0 + 0],
                     head_b[o0 + 1] + skip_b[o0 + 1]);
    ull acc1 = pack2(head_b[o0 + 2] + skip_b[o0 + 2],
                     head_b[o0 + 3] + skip_b[o0 + 3]);

    const float* ep = d_encT + n;
    const ulonglong2* w2 = (const ulonglong2*)sW;   // w2[f] = 4 packed o-weights

    #pragma unroll 1
    for (int c = 0; c < FAN_IN / 12; c++) {         // 21 chunks of 12
        const int f0 = c * 12;
        float ev[12];
        #pragma unroll
        for (int i = 0; i < 12; i++)
            ev[i] = __ldg(ep + (size_t)(f0 + i) * NCH);
        #pragma unroll
        for (int i = 0; i < 12; i++) {
            ull e2 = pack2(ev[i], ev[i]);
            ulonglong2 q = w2[f0 + i];
            acc0 = fma2(e2, q.x, acc0);
            acc1 = fma2(e2, q.y, acc1);
        }
    }
    __syncthreads();

    // stage skip weights transposed: sW[l*4 + oi] = skip_w[o0+oi][l]
    for (int idx = tid; idx < OTILE * SEQ_LEN; idx += 128) {
        int oi = idx >> 9, l = idx & 511;
        sW[l * OTILE + oi] = skip_w[(size_t)(o0 + oi) * SEQ_LEN + l];
    }
    __syncthreads();

    const float* xp = x + (size_t)b * (SEQ_LEN*CHANS) + m;
    #pragma unroll 1
    for (int c = 0; c < SEQ_LEN / 16; c++) {        // 32 chunks of 16
        const int l0 = c * 16;
        float xv[16];
        #pragma unroll
        for (int i = 0; i < 16; i++)
            xv[i] = __ldg(xp + (size_t)(l0 + i) * CHANS);
        #pragma unroll
        for (int i = 0; i < 16; i++) {
            ull x2 = pack2(xv[i], xv[i]);
            ulonglong2 q = w2[l0 + i];
            acc0 = fma2(x2, q.x, acc0);
            acc1 = fma2(x2, q.y, acc1);
        }
    }

    float* op = out + (size_t)b * (PRED_LEN*CHANS) + (size_t)o0 * CHANS + m;
    op[0*CHANS] = lo2(acc0);
    op[1*CHANS] = hi2(acc0);
    op[2*CHANS] = lo2(acc1);
    op[3*CHANS] = hi2(acc1);
}

// ---------------------------------------------------------------------------
extern "C" void kernel_launch(void* const* d_in, const int* in_sizes, int n_in,
                              void* d_out, int out_size) {
    const float* x       = (const float*)d_in[0];
    const float* weights = (const float*)d_in[1];
    const float* head_w  = (const float*)d_in[2];
    const float* head_b  = (const float*)d_in[3];
    const float* skip_w  = (const float*)d_in[4];
    const float* skip_b  = (const float*)d_in[5];
    float* out = (float*)d_out;

    enc_kernel<<<(NPATCH * NCH / 2) / 256, 256>>>(x, weights);
    out_kernel<<<dim3(PRED_LEN / OTILE, BATCH), 128>>>(x, head_w, head_b, skip_w, skip_b, out);
}